// round 13
// baseline (speedup 1.0000x reference)
#include <cuda_runtime.h>
#include <cuda_bf16.h>

#define THREADS  256
#define NWARP    (THREADS / 32)
#define WIN      9
#define EDGE     4
#define NPASS    8          // table split into 8 ranges of 256 bins (64 KB rows each)

__global__ __launch_bounds__(THREADS, 8)
void hwnet_kernel(const float* __restrict__ x,
                  const float* __restrict__ etab,
                  const float* __restrict__ tctab,
                  const float* __restrict__ vtab,
                  float* __restrict__ out,
                  int B, int T, int QBLK)
{
    // smem layout: ints first, then floats, then shorts -> all naturally aligned
    extern __shared__ char smem_raw[];
    int*   s_cnt = (int*)smem_raw;                   // [NPASS]
    int*   s_cur = s_cnt + NPASS;                    // [NPASS]
    float* s_x   = (float*)(s_cur + NPASS);          // [QBLK]
    short* s_idx = (short*)(s_x + QBLK);             // [QBLK]
    short* s_ord = s_idx + QBLK;                     // [QBLK]

    const int tid  = threadIdx.x;
    const int lane = tid & 31;
    const int warp = tid >> 5;
    const int q0   = blockIdx.x * QBLK;
    const int nq   = min(QBLK, B - q0);
    if (nq <= 0) return;

    const int shift = 31 - __clz((T + NPASS - 1) / NPASS);   // log2(256) = 8 for T=2048

    // ---- setup: idx per query (exact numerics), stage x, 8-bin histogram
    if (tid < NPASS) { s_cnt[tid] = 0; }
    __syncthreads();

    for (int i = tid; i < nq; i += THREADS) {
        const float xv = x[q0 + i];
        const float e0 = __ldg(&etab[0]);
        const float eN = __ldg(&etab[T - 1]);
        const float inv_step = (float)(T - 1) / (eN - e0);
        int i0 = (int)floorf((xv - e0) * inv_step);
        int idx = 0;
        float best = 3.4e38f;
        #pragma unroll
        for (int k = 0; k < 4; k++) {
            int cc = min(max(i0 - 1 + k, 0), T - 1);
            float d = xv - __ldg(&etab[cc]);
            d *= d;
            if (d < best) { best = d; idx = cc; }   // strict '<' == argmin first-occurrence
        }
        s_x[i]   = xv;
        s_idx[i] = (short)idx;
        atomicAdd(&s_cnt[idx >> shift], 1);
    }
    __syncthreads();

    // ---- tiny 8-bin exclusive scan (thread 0)
    if (tid == 0) {
        int run = 0;
        #pragma unroll
        for (int p = 0; p < NPASS; p++) { s_cur[p] = run; run += s_cnt[p]; }
    }
    __syncthreads();

    // ---- bucket scatter (smem cursors; order within bucket irrelevant)
    for (int i = tid; i < nq; i += THREADS) {
        int pos = atomicAdd(&s_cur[s_idx[i] >> shift], 1);
        s_ord[pos] = (short)i;
    }
    __syncthreads();
    // s_cur[p] now = end of bucket p; start = end - cnt (computed per pass below)

    // ---- passes: all blocks sweep table ranges in the same order (L1 time-locality)
    const int qsel = lane >> 3;        // 0..3: which of the warp's 4 queries
    const int sub  = lane & 7;         // 0..7: 16B chunk of D=64
    const float4* vt = (const float4*)vtab;

    #pragma unroll 1
    for (int p = 0; p < NPASS; p++) {
        const int cnt  = s_cnt[p];
        const int boff = s_cur[p] - cnt;

        for (int it = warp * 4; it < cnt; it += NWARP * 4) {
            float wv[WIN];
            int qid = -1, bb = 0;
            if (lane < 4 && it + lane < cnt) {
                qid = s_ord[boff + it + lane];
                const float xv = s_x[qid];
                const int idx = s_idx[qid];
                const float tc = __ldg(&tctab[idx]);           // UNCLIPPED idx (matches ref)
                bb = min(max(idx, EDGE), T - 1 - EDGE) - EDGE;

                float m = -3.4e38f;
                #pragma unroll
                for (int j = 0; j < WIN; j++) {
                    float e = __ldg(&etab[bb + j]);
                    float d = xv - e;
                    float l = -(d * d) * tc;
                    wv[j] = l;
                    m = fmaxf(m, l);
                }
                float sum = 0.0f;
                #pragma unroll
                for (int j = 0; j < WIN; j++) {
                    float pp = __expf(wv[j] - m);
                    wv[j] = pp;
                    sum += pp;
                }
                const float inv = __frcp_rn(sum);
                #pragma unroll
                for (int j = 0; j < WIN; j++) wv[j] *= inv;
            }

            bb  = __shfl_sync(0xffffffffu, bb,  qsel);
            qid = __shfl_sync(0xffffffffu, qid, qsel);
            #pragma unroll
            for (int j = 0; j < WIN; j++) wv[j] = __shfl_sync(0xffffffffu, wv[j], qsel);

            if (qid >= 0) {
                float4 a0 = make_float4(0.f, 0.f, 0.f, 0.f);
                float4 a1 = make_float4(0.f, 0.f, 0.f, 0.f);
                #pragma unroll
                for (int j = 0; j < WIN; j++) {
                    const float4* row = vt + (size_t)(bb + j) * 16;
                    float4 v0 = __ldg(row + sub);
                    float4 v1 = __ldg(row + 8 + sub);
                    float wj = wv[j];
                    a0.x = fmaf(wj, v0.x, a0.x);
                    a0.y = fmaf(wj, v0.y, a0.y);
                    a0.z = fmaf(wj, v0.z, a0.z);
                    a0.w = fmaf(wj, v0.w, a0.w);
                    a1.x = fmaf(wj, v1.x, a1.x);
                    a1.y = fmaf(wj, v1.y, a1.y);
                    a1.z = fmaf(wj, v1.z, a1.z);
                    a1.w = fmaf(wj, v1.w, a1.w);
                }
                float4* o = (float4*)(out + (size_t)(q0 + qid) * 64);
                __stcs(o + sub,     a0);
                __stcs(o + 8 + sub, a1);
            }
        }
    }
}

extern "C" void kernel_launch(void* const* d_in, const int* in_sizes, int n_in,
                              void* d_out, int out_size)
{
    const float* x     = (const float*)d_in[0];   // [B,1]
    const float* etab  = (const float*)d_in[1];   // [T,1]
    const float* tctab = (const float*)d_in[2];   // [T,1]
    const float* vtab  = (const float*)d_in[3];   // [T,D]
    float* out = (float*)d_out;

    const int B = in_sizes[0];                    // 131072
    const int T = in_sizes[1];                    // 2048

    const int BLOCKS = 148 * 8;                   // exactly one wave at 8 blocks/SM
    const int QBLK   = (B + BLOCKS - 1) / BLOCKS; // 111

    // dynamic smem: 2*NPASS ints + x[QBLK] floats + 2*QBLK shorts
    size_t sh = 2 * NPASS * sizeof(int) + QBLK * sizeof(float)
              + 2 * QBLK * sizeof(short) + 16;

    hwnet_kernel<<<BLOCKS, THREADS, sh>>>(x, etab, tctab, vtab, out, B, T, QBLK);
}

// round 15
// speedup vs baseline: 1.9152x; 1.9152x over previous
#include <cuda_runtime.h>
#include <cuda_fp16.h>

#define THREADS 256
#define WIN     9
#define EDGE    4
#define QPW     4          // queries per warp (8 lanes each)
#define VT_CAP  (2048 * 64)

__device__ __half g_vh[VT_CAP];   // fp16 copy of vector_table (rebuilt every launch)

// ---------- pre-pass: fp32 -> fp16 table conversion ----------
__global__ __launch_bounds__(256)
void k_cvt(const float* __restrict__ v, int n)
{
    int i = blockIdx.x * blockDim.x + threadIdx.x;
    if (i < n) g_vh[i] = __float2half_rn(v[i]);
}

__global__ __launch_bounds__(THREADS)
void hwnet_kernel(const float* __restrict__ x,
                  const float* __restrict__ etab,
                  const float* __restrict__ tctab,
                  float* __restrict__ out,
                  int B, int T)
{
    const int tid  = threadIdx.x;
    const int warp = tid >> 5;
    const int lane = tid & 31;
    const int qwarp = (blockIdx.x * (THREADS / 32) + warp) * QPW;

    // ---- Phase 1 (lanes 0..3): analytic nearest-idx + exact argmin + softmax (fp32 exact)
    float wv[WIN];
    int base = 0;
    if (lane < QPW) {
        const int q = qwarp + lane;
        const float xv = x[min(q, B - 1)];

        const float e0 = __ldg(&etab[0]);
        const float eN = __ldg(&etab[T - 1]);
        const float inv_step = (float)(T - 1) / (eN - e0);
        int i0 = (int)floorf((xv - e0) * inv_step);

        int idx = 0;
        float best = 3.4e38f;
        #pragma unroll
        for (int k = 0; k < 4; k++) {
            int cc = min(max(i0 - 1 + k, 0), T - 1);
            float d = xv - __ldg(&etab[cc]);
            d *= d;
            if (d < best) { best = d; idx = cc; }   // strict '<' == argmin first-occurrence
        }

        const float tc = __ldg(&tctab[idx]);        // UNCLIPPED idx (matches reference)
        base = min(max(idx, EDGE), T - 1 - EDGE) - EDGE;

        float m = -3.4e38f;
        #pragma unroll
        for (int j = 0; j < WIN; j++) {
            float e = __ldg(&etab[base + j]);
            float d = xv - e;
            float l = -(d * d) * tc;
            wv[j] = l;
            m = fmaxf(m, l);
        }
        float sum = 0.0f;
        #pragma unroll
        for (int j = 0; j < WIN; j++) {
            float p = __expf(wv[j] - m);
            wv[j] = p;
            sum += p;
        }
        const float inv = __frcp_rn(sum);
        #pragma unroll
        for (int j = 0; j < WIN; j++) wv[j] *= inv;
    }

    // ---- Broadcast to the 8 lanes owning each query
    const int q   = lane >> 3;      // 0..3
    const int sub = lane & 7;       // 0..7: which 16B (8-half) chunk of D=64
    base = __shfl_sync(0xffffffffu, base, q);
    #pragma unroll
    for (int j = 0; j < WIN; j++) wv[j] = __shfl_sync(0xffffffffu, wv[j], q);

    const int gq = qwarp + q;
    if (gq >= B) return;

    // ---- Phase 2: fp16 gather (one 128B line per row), fp32 accumulate
    const uint4* vt = (const uint4*)g_vh;           // 8 uint4 per 64-half row
    float a[8] = {0.f, 0.f, 0.f, 0.f, 0.f, 0.f, 0.f, 0.f};

    #pragma unroll
    for (int j = 0; j < WIN; j++) {
        uint4 h = __ldg(vt + (size_t)(base + j) * 8 + sub);
        const float wj = wv[j];
        float2 f;
        f = __half22float2(*(__half2*)&h.x);
        a[0] = fmaf(wj, f.x, a[0]);  a[1] = fmaf(wj, f.y, a[1]);
        f = __half22float2(*(__half2*)&h.y);
        a[2] = fmaf(wj, f.x, a[2]);  a[3] = fmaf(wj, f.y, a[3]);
        f = __half22float2(*(__half2*)&h.z);
        a[4] = fmaf(wj, f.x, a[4]);  a[5] = fmaf(wj, f.y, a[5]);
        f = __half22float2(*(__half2*)&h.w);
        a[6] = fmaf(wj, f.x, a[6]);  a[7] = fmaf(wj, f.y, a[7]);
    }

    // lane sub owns output floats [sub*8 .. sub*8+7] (contiguous, coalesced)
    float4* o = (float4*)(out + (size_t)gq * 64 + sub * 8);
    __stcs(o,     make_float4(a[0], a[1], a[2], a[3]));
    __stcs(o + 1, make_float4(a[4], a[5], a[6], a[7]));
}

extern "C" void kernel_launch(void* const* d_in, const int* in_sizes, int n_in,
                              void* d_out, int out_size)
{
    const float* x     = (const float*)d_in[0];   // [B,1]
    const float* etab  = (const float*)d_in[1];   // [T,1]
    const float* tctab = (const float*)d_in[2];   // [T,1]
    const float* vtab  = (const float*)d_in[3];   // [T,D]
    float* out = (float*)d_out;

    const int B  = in_sizes[0];                   // 131072
    const int T  = in_sizes[1];                   // 2048
    const int nv = min(in_sizes[3], VT_CAP);      // 131072 table elements

    k_cvt<<<(nv + 255) / 256, 256>>>(vtab, nv);

    const int qpb    = (THREADS / 32) * QPW;      // 32 queries per block
    const int blocks = (B + qpb - 1) / qpb;
    hwnet_kernel<<<blocks, THREADS>>>(x, etab, tctab, out, B, T);
}

// round 16
// speedup vs baseline: 2.1023x; 1.0977x over previous
#include <cuda_runtime.h>
#include <cuda_fp16.h>

#define THREADS 256
#define WIN     9
#define EDGE    4
#define QPW     4          // queries per warp (8 lanes each)
#define VT_CAP  (2048 * 64)

__device__ __half g_vh[VT_CAP];   // fp16 copy of vector_table (rebuilt every launch)

// ---------- pre-pass: fp32 -> fp16 table conversion (8 elems/thread, vectorized) ----------
__global__ __launch_bounds__(256)
void k_cvt(const float* __restrict__ v, int n8)
{
    int i = blockIdx.x * blockDim.x + threadIdx.x;   // one per 8 elements
    if (i >= n8) return;
    const float4* src = (const float4*)v + 2 * (size_t)i;
    float4 f0 = __ldg(src);
    float4 f1 = __ldg(src + 1);
    __half2 h0 = __floats2half2_rn(f0.x, f0.y);
    __half2 h1 = __floats2half2_rn(f0.z, f0.w);
    __half2 h2 = __floats2half2_rn(f1.x, f1.y);
    __half2 h3 = __floats2half2_rn(f1.z, f1.w);
    uint4 o;
    o.x = *(unsigned*)&h0; o.y = *(unsigned*)&h1;
    o.z = *(unsigned*)&h2; o.w = *(unsigned*)&h3;
    ((uint4*)g_vh)[i] = o;
}

// packed f32x2 helpers (sm_103a FFMA2 — PTX-only, ptxas won't auto-fuse)
__device__ __forceinline__ unsigned long long pack2(float lo, float hi) {
    unsigned long long r;
    asm("mov.b64 %0, {%1, %2};" : "=l"(r) : "f"(lo), "f"(hi));
    return r;
}
__device__ __forceinline__ void ffma2(unsigned long long& acc,
                                      unsigned long long a, unsigned long long b) {
    asm("fma.rn.f32x2 %0, %1, %2, %0;" : "+l"(acc) : "l"(a), "l"(b));
}
__device__ __forceinline__ float2 unpack2(unsigned long long v) {
    float2 f;
    asm("mov.b64 {%0, %1}, %2;" : "=f"(f.x), "=f"(f.y) : "l"(v));
    return f;
}

__global__ __launch_bounds__(THREADS)
void hwnet_kernel(const float* __restrict__ x,
                  const float* __restrict__ etab,
                  const float* __restrict__ tctab,
                  float* __restrict__ out,
                  int B, int T)
{
    const int tid  = threadIdx.x;
    const int warp = tid >> 5;
    const int lane = tid & 31;
    const int qwarp = (blockIdx.x * (THREADS / 32) + warp) * QPW;

    // ---- Phase 1 (lanes 0..3): analytic nearest-idx + exact argmin + softmax (fp32 exact)
    float wv[WIN];
    int base = 0;
    if (lane < QPW) {
        const int q = qwarp + lane;
        const float xv = x[min(q, B - 1)];

        const float e0 = __ldg(&etab[0]);
        const float eN = __ldg(&etab[T - 1]);
        const float inv_step = (float)(T - 1) / (eN - e0);
        int i0 = (int)floorf((xv - e0) * inv_step);

        int idx = 0;
        float best = 3.4e38f;
        #pragma unroll
        for (int k = 0; k < 4; k++) {
            int cc = min(max(i0 - 1 + k, 0), T - 1);
            float d = xv - __ldg(&etab[cc]);
            d *= d;
            if (d < best) { best = d; idx = cc; }   // strict '<' == argmin first-occurrence
        }

        const float tc = __ldg(&tctab[idx]);        // UNCLIPPED idx (matches reference)
        base = min(max(idx, EDGE), T - 1 - EDGE) - EDGE;

        float m = -3.4e38f;
        #pragma unroll
        for (int j = 0; j < WIN; j++) {
            float e = __ldg(&etab[base + j]);
            float d = xv - e;
            float l = -(d * d) * tc;
            wv[j] = l;
            m = fmaxf(m, l);
        }
        float sum = 0.0f;
        #pragma unroll
        for (int j = 0; j < WIN; j++) {
            float p = __expf(wv[j] - m);
            wv[j] = p;
            sum += p;
        }
        const float inv = __frcp_rn(sum);
        #pragma unroll
        for (int j = 0; j < WIN; j++) wv[j] *= inv;
    }

    // ---- Broadcast to the 8 lanes owning each query
    const int q   = lane >> 3;      // 0..3
    const int sub = lane & 7;       // 0..7: which 16B (8-half) chunk of D=64
    base = __shfl_sync(0xffffffffu, base, q);
    #pragma unroll
    for (int j = 0; j < WIN; j++) wv[j] = __shfl_sync(0xffffffffu, wv[j], q);

    const int gq = qwarp + q;
    if (gq >= B) return;

    // ---- Phase 2: fp16 gather (one 128B line per row), packed f32x2 accumulate
    const uint4* vt = (const uint4*)g_vh;           // 8 uint4 per 64-half row
    unsigned long long acc0 = pack2(0.f, 0.f);
    unsigned long long acc1 = acc0, acc2 = acc0, acc3 = acc0;

    #pragma unroll
    for (int j = 0; j < WIN; j++) {
        uint4 h = __ldg(vt + (size_t)(base + j) * 8 + sub);
        const float wj = wv[j];
        unsigned long long w2 = pack2(wj, wj);
        float2 f0 = __half22float2(*(__half2*)&h.x);
        float2 f1 = __half22float2(*(__half2*)&h.y);
        float2 f2 = __half22float2(*(__half2*)&h.z);
        float2 f3 = __half22float2(*(__half2*)&h.w);
        ffma2(acc0, pack2(f0.x, f0.y), w2);
        ffma2(acc1, pack2(f1.x, f1.y), w2);
        ffma2(acc2, pack2(f2.x, f2.y), w2);
        ffma2(acc3, pack2(f3.x, f3.y), w2);
    }

    float2 r0 = unpack2(acc0), r1 = unpack2(acc1);
    float2 r2 = unpack2(acc2), r3 = unpack2(acc3);

    // lane sub owns output floats [sub*8 .. sub*8+7] (contiguous, coalesced)
    float4* o = (float4*)(out + (size_t)gq * 64 + sub * 8);
    __stcs(o,     make_float4(r0.x, r0.y, r1.x, r1.y));
    __stcs(o + 1, make_float4(r2.x, r2.y, r3.x, r3.y));
}

extern "C" void kernel_launch(void* const* d_in, const int* in_sizes, int n_in,
                              void* d_out, int out_size)
{
    const float* x     = (const float*)d_in[0];   // [B,1]
    const float* etab  = (const float*)d_in[1];   // [T,1]
    const float* tctab = (const float*)d_in[2];   // [T,1]
    const float* vtab  = (const float*)d_in[3];   // [T,D]
    float* out = (float*)d_out;

    const int B  = in_sizes[0];                   // 131072
    const int T  = in_sizes[1];                   // 2048
    const int nv = min(in_sizes[3], VT_CAP);      // 131072 table elements
    const int n8 = nv / 8;                        // 16384 vectorized units

    k_cvt<<<(n8 + 255) / 256, 256>>>(vtab, n8);

    const int qpb    = (THREADS / 32) * QPW;      // 32 queries per block
    const int blocks = (B + qpb - 1) / qpb;
    hwnet_kernel<<<blocks, THREADS>>>(x, etab, tctab, out, B, T);
}